// round 15
// baseline (speedup 1.0000x reference)
#include <cuda_runtime.h>

#define T_STEPS 256
#define BATCH   64
#define IN_DIM  512
#define HID     1024
#define MDIM    2048
#define NB      128
#define NTF     512
#define BM      (BATCH*MDIM)   // 131072
#define BH      (BATCH*HID)    // 65536
#define AS_STR  68
#define BS_STR  260
#define AS_SZ   (16*AS_STR)    // 1088 floats
#define BS_SZ   (16*BS_STR)    // 4160 floats
#define SMEM_FLOATS (4*AS_SZ + 4*BS_SZ)   // 20992 floats = 83968 B

// ---------------- static device scratch ----------------
__device__ float g_xh[(size_t)T_STEPS * BH];  // x@Wxh + bh (64 MB)
__device__ float g_c[BH];                     // running c = m @ Wmh.T (red-accumulated)
__device__ unsigned g_cnt, g_gen;
__device__ unsigned cnt_c[4];     // per 256-col c tile: phase1 units done (sp1/step)
__device__ unsigned cnt_out[8];   // per 256-col out tile completion (step-ordered)
__device__ unsigned cnt_init[8];  // per 256-col out tile bm-init events

// ---------------- packed fp32x2 ----------------
__device__ __forceinline__ unsigned long long pack2(float a) {
    unsigned long long r;
    asm("mov.b64 %0, {%1, %1};" : "=l"(r) : "f"(a));
    return r;
}
__device__ __forceinline__ void ffma2(unsigned long long& c, unsigned long long a, unsigned long long b) {
    asm("fma.rn.f32x2 %0, %1, %2, %0;" : "+l"(c) : "l"(a), "l"(b));
}

// ---------------- L2-side vector reduction ----------------
__device__ __forceinline__ void red_add_v4(float* p, float4 v) {
    asm volatile("red.global.add.v4.f32 [%0], {%1,%2,%3,%4};"
                 :: "l"(p), "f"(v.x), "f"(v.y), "f"(v.z), "f"(v.w) : "memory");
}

// ---------------- sync primitives ----------------
__device__ __forceinline__ unsigned ldacq(const unsigned* p) {
    unsigned v;
    asm volatile("ld.acquire.gpu.global.u32 %0, [%1];" : "=r"(v) : "l"(p) : "memory");
    return v;
}
__device__ __forceinline__ void halfbar(int id) {
    asm volatile("bar.sync %0, %1;" :: "r"(id), "r"(256) : "memory");
}
__device__ __forceinline__ void grid_barrier() {
    __threadfence();
    __syncthreads();
    if (threadIdx.x == 0) {
        volatile unsigned* vg = &g_gen;
        unsigned old = *vg;
        unsigned prev = atomicAdd(&g_cnt, 1u);
        if (prev == NB - 1) {
            atomicExch(&g_cnt, 0u);
            __threadfence();
            atomicAdd(&g_gen, 1u);
        } else {
            while (*vg == old) { __nanosleep(64); }
        }
    }
    __syncthreads();
}

__device__ __forceinline__ int kval_d(int t) { return t ? min(__ffs(t), 8) : 8; }
// phase3 splits: Kc = 3072/sp3 multiple of 16; units = kcur*sp3 <= 192
__device__ __forceinline__ int sp3_of(int k) {
    return (k == 1) ? 192 : (k == 2) ? 96 : (k == 3) ? 64 : (k == 4) ? 48
         : (k <= 6) ? 32 : 24;
}
// phase1 splits: Kc1 = kprev*256/sp1 multiple of 16; units = 4*sp1 <= 128
__device__ __forceinline__ int sp1_of(int k) {
    return (k == 1) ? 16 : (k == 3) ? 24 : (k == 5) ? 20 : (k == 7) ? 28 : 32;
}

// ---------------- tile compute: 64 rows x 256 cols, 256 thr, 8x8 ----------
// cols per thread: [tx*4, tx*4+4) and [128+tx*4, 128+tx*4+4)
__device__ __forceinline__ void tile84(const float* As, const float* Bs,
                                       int ty, int tx, unsigned long long acc[8][4]) {
#pragma unroll
    for (int kk = 0; kk < 16; kk++) {
        float4 a0 = *(const float4*)(As + kk * AS_STR + ty * 8);
        float4 a1 = *(const float4*)(As + kk * AS_STR + ty * 8 + 4);
        const unsigned long long* bp0 = (const unsigned long long*)(Bs + kk * BS_STR + tx * 4);
        const unsigned long long* bp1 = (const unsigned long long*)(Bs + kk * BS_STR + 128 + tx * 4);
        unsigned long long b0 = bp0[0], b1 = bp0[1], b2 = bp1[0], b3 = bp1[1];
        float as[8] = {a0.x, a0.y, a0.z, a0.w, a1.x, a1.y, a1.z, a1.w};
#pragma unroll
        for (int r = 0; r < 8; r++) {
            unsigned long long av = pack2(as[r]);
            ffma2(acc[r][0], av, b0);
            ffma2(acc[r][1], av, b1);
            ffma2(acc[r][2], av, b2);
            ffma2(acc[r][3], av, b3);
        }
    }
}
// ---------------- 64x256, 256 thr, 8x8 (prologue) ----------
__device__ __forceinline__ void tile_compute8(const float* As, const float* Bs,
                                              int ty, int tx, unsigned long long acc[8][4]) {
#pragma unroll
    for (int kk = 0; kk < 16; kk++) {
        float4 a0 = *(const float4*)(As + kk * 68 + ty * 8);
        float4 a1 = *(const float4*)(As + kk * 68 + ty * 8 + 4);
        const unsigned long long* bp = (const unsigned long long*)(Bs + kk * 260 + tx * 8);
        unsigned long long b0 = bp[0], b1 = bp[1], b2 = bp[2], b3 = bp[3];
        float as[8] = {a0.x, a0.y, a0.z, a0.w, a1.x, a1.y, a1.z, a1.w};
#pragma unroll
        for (int r = 0; r < 8; r++) {
            unsigned long long av = pack2(as[r]);
            ffma2(acc[r][0], av, b0);
            ffma2(acc[r][1], av, b1);
            ffma2(acc[r][2], av, b2);
            ffma2(acc[r][3], av, b3);
        }
    }
}

// ---------------- prologue: g_xh = x @ Wxh + bh ----------------
__global__ __launch_bounds__(256) void xh_kernel(
    const float* __restrict__ X, const float* __restrict__ Wxh, const float* __restrict__ bh)
{
    __shared__ float As[16 * 68];
    __shared__ float Bs[16 * 260];
    const int tid = threadIdx.x;
    const int ty = tid >> 5, tx = tid & 31;
    const int colBase = blockIdx.x * 256;
    const int rowBase = blockIdx.y * 64;

    unsigned long long acc[8][4];
#pragma unroll
    for (int r = 0; r < 8; r++)
#pragma unroll
        for (int c = 0; c < 4; c++) acc[r][c] = 0ULL;

    for (int ch = 0; ch < 32; ch++) {
        int kb = ch << 4;
        {
            int row = tid >> 2, kl = (tid & 3) << 2;
            float4 v = *(const float4*)(X + (size_t)(rowBase + row) * IN_DIM + kb + kl);
            As[(kl + 0) * 68 + row] = v.x; As[(kl + 1) * 68 + row] = v.y;
            As[(kl + 2) * 68 + row] = v.z; As[(kl + 3) * 68 + row] = v.w;
        }
#pragma unroll
        for (int i = 0; i < 4; i++) {
            int g = tid + i * 256;
            int kl = g >> 6, col4 = (g & 63) << 2;
            float4 v = *(const float4*)(Wxh + (size_t)(kb + kl) * HID + colBase + col4);
            *(float4*)(Bs + kl * 260 + col4) = v;
        }
        __syncthreads();
        tile_compute8(As, Bs, ty, tx, acc);
        __syncthreads();
    }
#pragma unroll
    for (int r = 0; r < 8; r++) {
        int row = rowBase + ty * 8 + r;
        int jg = colBase + tx * 8;
#pragma unroll
        for (int c = 0; c < 4; c++) {
            float2 v = *(float2*)&acc[r][c];
            float2 bb = *(const float2*)(bh + jg + c * 2);
            v.x += bb.x; v.y += bb.y;
            *(float2*)(g_xh + (size_t)row * HID + jg + c * 2) = v;
        }
    }
}

// ======== shared load/store macros ========
#define PX_STORE(AP, BP, BF) do { float* A_ = (AP) + (BF) * AS_SZ; float* B_ = (BP) + (BF) * BS_SZ; \
    A_[(akl + 0) * AS_STR + arow] = aR.x; A_[(akl + 1) * AS_STR + arow] = aR.y;            \
    A_[(akl + 2) * AS_STR + arow] = aR.z; A_[(akl + 3) * AS_STR + arow] = aR.w;            \
    _Pragma("unroll")                                                                      \
    for (int i_ = 0; i_ < 4; i_++) { int c_ = arow + 64 * i_;                              \
        B_[(akl + 0) * BS_STR + c_] = bRv[i_].x; B_[(akl + 1) * BS_STR + c_] = bRv[i_].y;  \
        B_[(akl + 2) * BS_STR + c_] = bRv[i_].z; B_[(akl + 3) * BS_STR + c_] = bRv[i_].w; }\
} while (0)

#define P3_LOADB(CH) do { int kb = kb0 + ((CH) << 4);                                      \
    _Pragma("unroll")                                                                      \
    for (int i_ = 0; i_ < 4; i_++) { int jg = colBase + arow + 64 * i_;                    \
        bRv[i_] = (kb < MDIM) ? *(const float4*)(Wmm + (size_t)jg * MDIM + kb + akl)       \
                              : *(const float4*)(Whm + (size_t)jg * HID + (kb - MDIM) + akl); } \
} while (0)

#define P3_LOADA(CH) do { int kb = kb0 + ((CH) << 4);                                      \
    if (kb < MDIM) {                                                                       \
        aR = __ldcg((const float4*)(mP + (size_t)arow * MDIM + kb + akl));                 \
    } else {                                                                               \
        size_t hoff = (size_t)arow * HID + (kb - MDIM) + akl;                              \
        float4 cc = __ldcg((const float4*)(g_c + hoff));                                   \
        float4 xx = *(const float4*)(g_xh + (size_t)t * BH + hoff);                        \
        aR = make_float4(tanhf(xx.x + cc.x), tanhf(xx.y + cc.y),                           \
                         tanhf(xx.z + cc.z), tanhf(xx.w + cc.w));                          \
    }                                                                                      \
} while (0)

// ======== phase-3 unit body ========
// scope: unit, t, sp3, cum_c, mP, Wmm, Whm, out, eo, eI, lead, ty, tx, arow, akl
#define PHASE3_BODY(AP, BP, BARID)                                                         \
{                                                                                          \
    const int Kc3 = 3072 / sp3;                                                            \
    const int chunks = Kc3 >> 4;                                                           \
    const int ct256 = unit / sp3;                                                          \
    const int s = unit - ct256 * sp3;                                                      \
    const int colBase = ct256 * 256;                                                       \
    const int kb0 = s * Kc3;                                                               \
    const int kend = kb0 + Kc3;                                                            \
    const int hstart = (kb0 >= MDIM) ? 0 : ((kend <= MDIM) ? chunks : ((MDIM - kb0) >> 4));\
    float4 aR = make_float4(0.f,0.f,0.f,0.f);                                              \
    float4 bRv[4];                                                                         \
    P3_LOADB(0);   /* weight prefetch overlaps the waits */                                \
    if (lead) {                                                                            \
        while (ldacq(&cnt_init[ct256]) < (unsigned)eI[ct256]) { }                          \
        const int mk1 = min(kend, MDIM);                                                   \
        if (t && mk1 > kb0) {                                                              \
            const int jlo = kb0 >> 8, jhi = (mk1 - 1) >> 8;                                \
            for (int j = jlo; j <= jhi; j++)                                               \
                while (ldacq(&cnt_out[j]) < (unsigned)eo[j]) { }                           \
        }                                                                                  \
        if (hstart == 0) {                                                                 \
            const int jlo = (kb0 - MDIM) >> 8, jhi = (kend - 1 - MDIM) >> 8;               \
            for (int j = jlo; j <= jhi; j++)                                               \
                while (ldacq(&cnt_c[j]) < (unsigned)cum_c) { }                             \
        }                                                                                  \
    }                                                                                      \
    halfbar(BARID);                                                                        \
    unsigned long long acc[8][4];                                                          \
    _Pragma("unroll")                                                                      \
    for (int r = 0; r < 8; r++)                                                            \
        { acc[r][0] = 0ULL; acc[r][1] = 0ULL; acc[r][2] = 0ULL; acc[r][3] = 0ULL; }        \
    P3_LOADA(0); PX_STORE(AP, BP, 0); halfbar(BARID);                                      \
    for (int ch = 0; ch < chunks; ch++) {                                                  \
        if (ch + 1 < chunks) {                                                             \
            if (ch + 1 == hstart) {                                                        \
                if (lead) {                                                                \
                    const int jhi2 = (kend - 1 - MDIM) >> 8;                               \
                    for (int j = 0; j <= jhi2; j++)                                        \
                        while (ldacq(&cnt_c[j]) < (unsigned)cum_c) { }                     \
                }                                                                          \
                halfbar(BARID);                                                            \
            }                                                                              \
            P3_LOADB(ch + 1); P3_LOADA(ch + 1);                                            \
        }                                                                                  \
        tile84((AP) + (ch & 1) * AS_SZ, (BP) + (ch & 1) * BS_SZ, ty, tx, acc);             \
        if (ch + 1 < chunks) { PX_STORE(AP, BP, (ch + 1) & 1); halfbar(BARID); }           \
    }                                                                                      \
    {                                                                                      \
        float* obase = out + (size_t)t * BM;                                               \
        _Pragma("unroll")                                                                  \
        for (int r = 0; r < 8; r++) {                                                      \
            float2 a0 = *(float2*)&acc[r][0], a1 = *(float2*)&acc[r][1];                   \
            float2 a2 = *(float2*)&acc[r][2], a3 = *(float2*)&acc[r][3];                   \
            float* p = obase + (size_t)(ty * 8 + r) * MDIM + colBase;                      \
            red_add_v4(p + tx * 4,       make_float4(a0.x, a0.y, a1.x, a1.y));             \
            red_add_v4(p + 128 + tx * 4, make_float4(a2.x, a2.y, a3.x, a3.y));             \
        }                                                                                  \
    }                                                                                      \
    if (lead) { while (ldacq(&cnt_out[ct256]) < (unsigned)eo[ct256]) { } }                 \
    __threadfence();                                                                       \
    halfbar(BARID);                                                                        \
    if (lead) atomicAdd(&cnt_out[ct256], 1u);                                              \
}

// ---------------- persistent dataflow recurrence ----------------
__global__ __launch_bounds__(NTF, 1) void rnn_persistent(
    const float* __restrict__ m_prev, const float* __restrict__ Wmh,
    const float* __restrict__ Wmm, const float* __restrict__ Whm,
    const float* __restrict__ bm, float* __restrict__ out)
{
    extern __shared__ float sm[];
    float* AsA = sm;
    float* BsA = sm + 2 * AS_SZ;
    float* AsB = sm + 2 * AS_SZ + 2 * BS_SZ;
    float* BsB = AsB + 2 * AS_SZ;

    const int tid = threadIdx.x;
    const int bid = blockIdx.x;

    // ---- startup: reset counters, zero g_c, out[0]=bm ----
    if (bid == 0 && tid == 0) {
#pragma unroll
        for (int i = 0; i < 4; i++) cnt_c[i] = 0;
#pragma unroll
        for (int i = 0; i < 8; i++) { cnt_out[i] = 0; cnt_init[i] = 0; }
    }
    {
        int ft = bid * NTF + tid;
        g_c[ft] = 0.0f;
        int col = (ft * 2) & (MDIM - 1);
        *(float2*)(out + (size_t)ft * 2) = *(const float2*)(bm + col);
    }
    grid_barrier();

    if (tid < 256) {
        // ============ HALF A: phase1 + bm-init + copies + phase3 overflow ============
        const int l = tid;
        const bool lead = (l == 0);
        const int ty = l >> 5, tx = l & 31;
        const int arow = l >> 2, akl = (l & 3) << 2;
        int eo[8], eI[8];
        unsigned cum_c = 0;
#pragma unroll
        for (int j = 0; j < 8; j++) { eo[j] = 0; eI[j] = 0; }

        for (int t = 0; t < T_STEPS; t++) {
            const float* mP  = t ? (out + (size_t)(t - 1) * BM) : m_prev;
            const float* mPP = (t >= 2) ? (out + (size_t)(t - 2) * BM) : m_prev;
            const int kcur  = kval_d(t);
            const int kprev = (t <= 1) ? 8 : kval_d(t - 1);
            const int sp3   = sp3_of(kcur);
            const int units = kcur * sp3;
            const int sp1   = sp1_of(kprev);
            const int Kc1   = kprev * 256 / sp1;
            const int ch1   = Kc1 >> 4;
            cum_c += (unsigned)sp1;

            // ---- phase1: red(dm @ Wmh.T) into g_c (4*sp1 units) ----
            if (bid < 4 * sp1) {
                const int ct4 = bid / sp1, s = bid - ct4 * sp1;
                const int kb0 = s * Kc1;
                const int colBase = ct4 * 256;
                float4 aR = make_float4(0.f,0.f,0.f,0.f);
                float4 bRv[4];

#define P1_LOADB(CH) do { int kb = kb0 + ((CH) << 4);                                      \
    _Pragma("unroll")                                                                      \
    for (int i_ = 0; i_ < 4; i_++) { int jg = colBase + arow + 64 * i_;                    \
        bRv[i_] = *(const float4*)(Wmh + (size_t)jg * MDIM + kb + akl); }                  \
} while (0)
#define P1_LOADA(CH) do { int kb = kb0 + ((CH) << 4);                                      \
    if (t) {                                                                               \
        float4 p = __ldcg((const float4*)(mP  + (size_t)arow * MDIM + kb + akl));          \
        float4 q = __ldcg((const float4*)(mPP + (size_t)arow * MDIM + kb + akl));          \
        aR = make_float4(p.x - q.x, p.y - q.y, p.z - q.z, p.w - q.w);                      \
    } else {                                                                               \
        aR = *(const float4*)(m_prev + (size_t)arow * MDIM + kb + akl);                    \
    }                                                                                      \
} while (0)

                P1_LOADB(0);          // prefetch weights before the waits
                if (t && lead) {
                    for (int j = 0; j < kprev; j++)
                        while (ldacq(&cnt_out[j]) < (unsigned)eo[j]) { }
                }
                halfbar(1);
                unsigned long long acc[8][4];
#pragma unroll
                for (int r = 0; r < 8; r++)
                    { acc[r][0] = 0ULL; acc[r][1] = 0ULL; acc[r][2] = 0ULL; acc[r][3] = 0ULL; }
                P1_LOADA(0); PX_STORE(AsA, BsA, 0); halfbar(1);
                for (int ch = 0; ch < ch1; ch++) {
                    if (ch + 1 < ch1) { P1_LOADB(ch + 1); P1_LOADA(ch + 1); }
                    tile84(AsA + (ch & 1) * AS_SZ, BsA + (ch & 1) * BS_SZ, ty, tx, acc);
                    if (ch + 1 < ch1) { PX_STORE(AsA, BsA, (ch + 1) & 1); halfbar(1); }
                }
#pragma unroll
                for (int r = 0; r < 8; r++) {
                    float2 a0 = *(float2*)&acc[r][0], a1 = *(float2*)&acc[r][1];
                    float2 a2 = *(float2*)&acc[r][2], a3 = *(float2*)&acc[r][3];
                    float* p = g_c + (size_t)(ty * 8 + r) * HID + colBase;
                    red_add_v4(p + tx * 4,       make_float4(a0.x, a0.y, a1.x, a1.y));
                    red_add_v4(p + 128 + tx * 4, make_float4(a2.x, a2.y, a3.x, a3.y));
                }
                __threadfence();
                halfbar(1);
                if (lead) atomicAdd(&cnt_c[ct4], 1u);
            }

            // ---- bm-init out[t+1] active tiles (blocks 0..7) ----
            if (t + 1 < T_STEPS && bid < 8) {
                int kn = kval_d(t + 1);
                if (bid < kn) {
                    float* dst = out + (size_t)(t + 1) * BM;
                    for (int idx = l; idx < 4096; idx += 256) {
                        int row = idx >> 6, c4 = (idx & 63) << 2;
                        *(float4*)(dst + (size_t)row * MDIM + bid * 256 + c4) =
                            *(const float4*)(bm + bid * 256 + c4);
                    }
                    __threadfence();
                    halfbar(1);
                    if (lead) atomicAdd(&cnt_init[bid], 1u);
                }
            }

            // ---- copies: inactive tiles (blocks 0..63; 8 x 32-col units per tile) ----
            if (bid < 64) {
                const int ct8 = bid >> 3, part = bid & 7;
                if (ct8 >= kcur) {
                    if (lead) { while (ldacq(&cnt_out[ct8]) < (unsigned)eo[ct8]) { } }
                    halfbar(1);
                    for (int idx = l; idx < 512; idx += 256) {
                        int row = idx >> 3;
                        int col = ct8 * 256 + part * 32 + (idx & 7) * 4;
                        size_t moff = (size_t)row * MDIM + col;
                        float4 v = __ldcg((const float4*)(mP + moff));
                        *(float4*)(out + (size_t)t * BM + moff) = v;
                    }
                    __threadfence();
                    halfbar(1);
                    if (lead) atomicAdd(&cnt_out[ct8], 1u);
                }
            }

            // ---- phase3 overflow (blocks 64..127 -> units 128..191) ----
            if (bid >= 64 && 64 + bid < units) {
                const int unit = 64 + bid;
                PHASE3_BODY(AsA, BsA, 1);
            }

            // ---- bookkeeping ----
#pragma unroll
            for (int j = 0; j < 8; j++) eo[j] += (j < kcur) ? sp3 : 8;
            if (t + 1 < T_STEPS) {
                int kn = kval_d(t + 1);
#pragma unroll
                for (int j = 0; j < 8; j++) if (j < kn) eI[j]++;
            }
        }

        // ---- final: m_T = out[255] ----
        if (lead) {
#pragma unroll
            for (int j = 0; j < 8; j++)
                while (ldacq(&cnt_out[j]) < (unsigned)eo[j]) { }
        }
        halfbar(1);
        {
            int ft2 = bid * 256 + l;
            float4 v = __ldcg((const float4*)(out + (size_t)(T_STEPS - 1) * BM + (size_t)ft2 * 4));
            *(float4*)(out + (size_t)T_STEPS * BM + (size_t)ft2 * 4) = v;
        }
    } else {
        // ============ HALF B: phase3 main units (0..127) ============
        const int l = tid - 256;
        const bool lead = (l == 0);
        const int ty = l >> 5, tx = l & 31;
        const int arow = l >> 2, akl = (l & 3) << 2;
        int eo[8], eI[8];
        unsigned cum_c = 0;
#pragma unroll
        for (int j = 0; j < 8; j++) { eo[j] = 0; eI[j] = 0; }

        for (int t = 0; t < T_STEPS; t++) {
            const float* mP = t ? (out + (size_t)(t - 1) * BM) : m_prev;
            const int kcur = kval_d(t);
            const int kprev = (t <= 1) ? 8 : kval_d(t - 1);
            const int sp3 = sp3_of(kcur);
            const int units = kcur * sp3;
            cum_c += (unsigned)sp1_of(kprev);
            if (bid < units) {
                const int unit = bid;
                PHASE3_BODY(AsB, BsB, 2);
            }
            // ---- bookkeeping ----
#pragma unroll
            for (int j = 0; j < 8; j++) eo[j] += (j < kcur) ? sp3 : 8;
            if (t + 1 < T_STEPS) {
                int kn = kval_d(t + 1);
#pragma unroll
                for (int j = 0; j < 8; j++) if (j < kn) eI[j]++;
            }
        }
    }
}

// ---------------- host ----------------
extern "C" void kernel_launch(void* const* d_in, const int* in_sizes, int n_in,
                              void* d_out, int out_size)
{
    const float* x      = (const float*)d_in[0];
    const float* m_prev = (const float*)d_in[1];
    const float* Wxh    = (const float*)d_in[2];
    const float* Whm    = (const float*)d_in[3];
    const float* Wmm    = (const float*)d_in[4];
    const float* Wmh    = (const float*)d_in[5];
    const float* bm     = (const float*)d_in[6];
    const float* bh     = (const float*)d_in[7];
    float* out = (float*)d_out;
    (void)in_sizes; (void)n_in; (void)out_size;

    cudaFuncSetAttribute(rnn_persistent,
                         cudaFuncAttributeMaxDynamicSharedMemorySize,
                         SMEM_FLOATS * sizeof(float));

    xh_kernel<<<dim3(4, 256), 256>>>(x, Wxh, bh);
    rnn_persistent<<<NB, NTF, SMEM_FLOATS * sizeof(float)>>>(m_prev, Wmh, Wmm, Whm, bm, out);
}

// round 16
// speedup vs baseline: 1.1111x; 1.1111x over previous
#include <cuda_runtime.h>

#define T_STEPS 256
#define BATCH   64
#define IN_DIM  512
#define HID     1024
#define MDIM    2048
#define NB      128
#define NTF     512
#define BM      (BATCH*MDIM)   // 131072
#define BH      (BATCH*HID)    // 65536
#define AS_STR  68
#define BS_STR  132
#define AS_SZ   (16*AS_STR)    // 1088 floats
#define BS_SZ   (16*BS_STR)    // 2112 floats
#define SMEM_FLOATS (4*AS_SZ + 4*BS_SZ)   // 12800 floats = 51200 B

// ---------------- static device scratch ----------------
__device__ float g_xh[(size_t)T_STEPS * BH];  // x@Wxh + bh (64 MB)
__device__ float g_c[BH];                     // running c = m @ Wmh.T (red-accumulated)
__device__ unsigned g_cnt, g_gen;
__device__ unsigned cnt_c[8];     // per 128-col c tile: phase1 units done (16/step)
__device__ unsigned cnt_out[8];   // per 256-col out tile completion (step-ordered)
__device__ unsigned cnt_init[8];  // per 256-col out tile bm-init events

// ---------------- packed fp32x2 ----------------
__device__ __forceinline__ unsigned long long pack2(float a) {
    unsigned long long r;
    asm("mov.b64 %0, {%1, %1};" : "=l"(r) : "f"(a));
    return r;
}
__device__ __forceinline__ void ffma2(unsigned long long& c, unsigned long long a, unsigned long long b) {
    asm("fma.rn.f32x2 %0, %1, %2, %0;" : "+l"(c) : "l"(a), "l"(b));
}

// ---------------- L2-side vector reduction ----------------
__device__ __forceinline__ void red_add_v4(float* p, float4 v) {
    asm volatile("red.global.add.v4.f32 [%0], {%1,%2,%3,%4};"
                 :: "l"(p), "f"(v.x), "f"(v.y), "f"(v.z), "f"(v.w) : "memory");
}

// ---------------- sync primitives ----------------
__device__ __forceinline__ unsigned ldacq(const unsigned* p) {
    unsigned v;
    asm volatile("ld.acquire.gpu.global.u32 %0, [%1];" : "=r"(v) : "l"(p) : "memory");
    return v;
}
__device__ __forceinline__ void halfbar(int id) {
    asm volatile("bar.sync %0, %1;" :: "r"(id), "r"(256) : "memory");
}
__device__ __forceinline__ void grid_barrier() {
    __threadfence();
    __syncthreads();
    if (threadIdx.x == 0) {
        volatile unsigned* vg = &g_gen;
        unsigned old = *vg;
        unsigned prev = atomicAdd(&g_cnt, 1u);
        if (prev == NB - 1) {
            atomicExch(&g_cnt, 0u);
            __threadfence();
            atomicAdd(&g_gen, 1u);
        } else {
            while (*vg == old) { __nanosleep(64); }
        }
    }
    __syncthreads();
}

__device__ __forceinline__ int kval_d(int t) { return t ? min(__ffs(t), 8) : 8; }
// units = 2*k*sp3 <= 256; Kc = 3072/sp3 is a multiple of 16
__device__ __forceinline__ int sp3_of(int k) {
    return (k == 1) ? 96 : (k == 2) ? 64 : (k <= 4) ? 32 : (k == 5) ? 24 : 16;
}

// ---------------- tile compute: 64 rows x 128 cols, 256 thr, 8x4 ----------
__device__ __forceinline__ void tile82(const float* As, const float* Bs,
                                       int ty, int tx, unsigned long long acc[8][2]) {
#pragma unroll
    for (int kk = 0; kk < 16; kk++) {
        float4 a0 = *(const float4*)(As + kk * AS_STR + ty * 8);
        float4 a1 = *(const float4*)(As + kk * AS_STR + ty * 8 + 4);
        const unsigned long long* bp = (const unsigned long long*)(Bs + kk * BS_STR + tx * 4);
        unsigned long long b0 = bp[0], b1 = bp[1];
        float as[8] = {a0.x, a0.y, a0.z, a0.w, a1.x, a1.y, a1.z, a1.w};
#pragma unroll
        for (int r = 0; r < 8; r++) {
            unsigned long long av = pack2(as[r]);
            ffma2(acc[r][0], av, b0);
            ffma2(acc[r][1], av, b1);
        }
    }
}
// ---------------- 64x256, 256 thr, 8x8 (prologue only) ----------
__device__ __forceinline__ void tile_compute8(const float* As, const float* Bs,
                                              int ty, int tx, unsigned long long acc[8][4]) {
#pragma unroll
    for (int kk = 0; kk < 16; kk++) {
        float4 a0 = *(const float4*)(As + kk * 68 + ty * 8);
        float4 a1 = *(const float4*)(As + kk * 68 + ty * 8 + 4);
        const unsigned long long* bp = (const unsigned long long*)(Bs + kk * 260 + tx * 8);
        unsigned long long b0 = bp[0], b1 = bp[1], b2 = bp[2], b3 = bp[3];
        float as[8] = {a0.x, a0.y, a0.z, a0.w, a1.x, a1.y, a1.z, a1.w};
#pragma unroll
        for (int r = 0; r < 8; r++) {
            unsigned long long av = pack2(as[r]);
            ffma2(acc[r][0], av, b0);
            ffma2(acc[r][1], av, b1);
            ffma2(acc[r][2], av, b2);
            ffma2(acc[r][3], av, b3);
        }
    }
}

// ---------------- prologue: g_xh = x @ Wxh + bh ----------------
__global__ __launch_bounds__(256) void xh_kernel(
    const float* __restrict__ X, const float* __restrict__ Wxh, const float* __restrict__ bh)
{
    __shared__ float As[16 * 68];
    __shared__ float Bs[16 * 260];
    const int tid = threadIdx.x;
    const int ty = tid >> 5, tx = tid & 31;
    const int colBase = blockIdx.x * 256;
    const int rowBase = blockIdx.y * 64;

    unsigned long long acc[8][4];
#pragma unroll
    for (int r = 0; r < 8; r++)
#pragma unroll
        for (int c = 0; c < 4; c++) acc[r][c] = 0ULL;

    for (int ch = 0; ch < 32; ch++) {
        int kb = ch << 4;
        {
            int row = tid >> 2, kl = (tid & 3) << 2;
            float4 v = *(const float4*)(X + (size_t)(rowBase + row) * IN_DIM + kb + kl);
            As[(kl + 0) * 68 + row] = v.x; As[(kl + 1) * 68 + row] = v.y;
            As[(kl + 2) * 68 + row] = v.z; As[(kl + 3) * 68 + row] = v.w;
        }
#pragma unroll
        for (int i = 0; i < 4; i++) {
            int g = tid + i * 256;
            int kl = g >> 6, col4 = (g & 63) << 2;
            float4 v = *(const float4*)(Wxh + (size_t)(kb + kl) * HID + colBase + col4);
            *(float4*)(Bs + kl * 260 + col4) = v;
        }
        __syncthreads();
        tile_compute8(As, Bs, ty, tx, acc);
        __syncthreads();
    }
#pragma unroll
    for (int r = 0; r < 8; r++) {
        int row = rowBase + ty * 8 + r;
        int jg = colBase + tx * 8;
#pragma unroll
        for (int c = 0; c < 4; c++) {
            float2 v = *(float2*)&acc[r][c];
            float2 bb = *(const float2*)(bh + jg + c * 2);
            v.x += bb.x; v.y += bb.y;
            *(float2*)(g_xh + (size_t)row * HID + jg + c * 2) = v;
        }
    }
}

// ======== phase-3 unit body (shared by both halves via macro) ========
// uses from scope: unit, t, kcur, sp3, mP, Wmm, Whm, out, eo, eI, lead,
// ty, tx, arow, akl
#define P3_LOADB(CH) do { int kb = kb0 + ((CH) << 4);                                      \
    { int jg = colBase + arow;                                                             \
      bR0 = (kb < MDIM) ? *(const float4*)(Wmm + (size_t)jg * MDIM + kb + akl)             \
                        : *(const float4*)(Whm + (size_t)jg * HID + (kb - MDIM) + akl); }  \
    { int jg = colBase + 64 + arow;                                                        \
      bR1 = (kb < MDIM) ? *(const float4*)(Wmm + (size_t)jg * MDIM + kb + akl)             \
                        : *(const float4*)(Whm + (size_t)jg * HID + (kb - MDIM) + akl); }  \
} while (0)

#define P3_LOADA(CH) do { int kb = kb0 + ((CH) << 4);                                      \
    if (kb < MDIM) {                                                                       \
        aR = __ldcg((const float4*)(mP + (size_t)arow * MDIM + kb + akl));                 \
    } else {                                                                               \
        size_t hoff = (size_t)arow * HID + (kb - MDIM) + akl;                              \
        float4 cc = __ldcg((const float4*)(g_c + hoff));                                   \
        float4 xx = *(const float4*)(g_xh + (size_t)t * BH + hoff);                        \
        aR = make_float4(tanhf(xx.x + cc.x), tanhf(xx.y + cc.y),                           \
                         tanhf(xx.z + cc.z), tanhf(xx.w + cc.w));                          \
    }                                                                                      \
} while (0)

#define PX_STORE(AP, BP, BF) do { float* A_ = (AP) + (BF) * AS_SZ; float* B_ = (BP) + (BF) * BS_SZ; \
    A_[(akl + 0) * AS_STR + arow] = aR.x; A_[(akl + 1) * AS_STR + arow] = aR.y;            \
    A_[(akl + 2) * AS_STR + arow] = aR.z; A_[(akl + 3) * AS_STR + arow] = aR.w;            \
    B_[(akl + 0) * BS_STR + arow] = bR0.x; B_[(akl + 1) * BS_STR + arow] = bR0.y;          \
    B_[(akl + 2) * BS_STR + arow] = bR0.z; B_[(akl + 3) * BS_STR + arow] = bR0.w;          \
    B_[(akl + 0) * BS_STR + 64 + arow] = bR1.x; B_[(akl + 1) * BS_STR + 64 + arow] = bR1.y;\
    B_[(akl + 2) * BS_STR + 64 + arow] = bR1.z; B_[(akl + 3) * BS_STR + 64 + arow] = bR1.w;\
} while (0)

#define PHASE3_BODY(AP, BP, BARID)                                                         \
{                                                                                          \
    const int Kc3 = 3072 / sp3;                                                            \
    const int chunks = Kc3 >> 4;                                                           \
    const int t128 = unit / sp3;                                                           \
    const int s = unit - t128 * sp3;                                                       \
    const int colBase = t128 * 128;                                                        \
    const int ct256 = t128 >> 1;                                                           \
    const int kb0 = s * Kc3;                                                               \
    const int kend = kb0 + Kc3;                                                            \
    const int hstart = (kb0 >= MDIM) ? 0 : ((kend <= MDIM) ? chunks : ((MDIM - kb0) >> 4));\
    float4 aR = make_float4(0.f,0.f,0.f,0.f);                                              \
    float4 bR0, bR1;                                                                       \
    P3_LOADB(0);   /* weight prefetch overlaps the waits */                                \
    if (lead) {                                                                            \
        while (ldacq(&cnt_init[ct256]) < (unsigned)eI[ct256]) { }                          \
        const int mk1 = min(kend, MDIM);                                                   \
        if (t && mk1 > kb0) {                                                              \
            const int jlo = kb0 >> 8, jhi = (mk1 - 1) >> 8;                                \
            for (int j = jlo; j <= jhi; j++)                                               \
                while (ldacq(&cnt_out[j]) < (unsigned)eo[j]) { }                           \
        }                                                                                  \
        if (hstart == 0) {                                                                 \
            const int jlo = (kb0 - MDIM) >> 7, jhi = (kend - 1 - MDIM) >> 7;               \
            for (int j = jlo; j <= jhi; j++)                                               \
                while (ldacq(&cnt_c[j]) < 16u * (unsigned)(t + 1)) { }                     \
        }                                                                                  \
    }                                                                                      \
    halfbar(BARID);                                                                        \
    unsigned long long acc[8][2];                                                          \
    _Pragma("unroll")                                                                      \
    for (int r = 0; r < 8; r++) { acc[r][0] = 0ULL; acc[r][1] = 0ULL; }                    \
    P3_LOADA(0); PX_STORE(AP, BP, 0); halfbar(BARID);                                      \
    for (int ch = 0; ch < chunks; ch++) {                                                  \
        if (ch + 1 < chunks) {                                                             \
            if (ch + 1 == hstart) {                                                        \
                if (lead) {                                                                \
                    const int jhi2 = (kend - 1 - MDIM) >> 7;                               \
                    for (int j = 0; j <= jhi2; j++)                                        \
                        while (ldacq(&cnt_c[j]) < 16u * (unsigned)(t + 1)) { }             \
                }                                                                          \
                halfbar(BARID);                                                            \
            }                                                                              \
            P3_LOADB(ch + 1); P3_LOADA(ch + 1);                                            \
        }                                                                                  \
        tile82((AP) + (ch & 1) * AS_SZ, (BP) + (ch & 1) * BS_SZ, ty, tx, acc);             \
        if (ch + 1 < chunks) { PX_STORE(AP, BP, (ch + 1) & 1); halfbar(BARID); }           \
    }                                                                                      \
    {                                                                                      \
        float* obase = out + (size_t)t * BM;                                               \
        _Pragma("unroll")                                                                  \
        for (int r = 0; r < 8; r++) {                                                      \
            float2 a0 = *(float2*)&acc[r][0], a1 = *(float2*)&acc[r][1];                   \
            red_add_v4(obase + (size_t)(ty * 8 + r) * MDIM + colBase + tx * 4,             \
                       make_float4(a0.x, a0.y, a1.x, a1.y));                               \
        }                                                                                  \
    }                                                                                      \
    /* step-ordering poll + fence + single bar + signal */                                 \
    if (lead) { while (ldacq(&cnt_out[ct256]) < (unsigned)eo[ct256]) { } }                 \
    __threadfence();                                                                       \
    halfbar(BARID);                                                                        \
    if (lead) atomicAdd(&cnt_out[ct256], 1u);                                              \
}

// ---------------- persistent dataflow recurrence (warp-specialized halves) ----
__global__ __launch_bounds__(NTF, 1) void rnn_persistent(
    const float* __restrict__ m_prev, const float* __restrict__ Wmh,
    const float* __restrict__ Wmm, const float* __restrict__ Whm,
    const float* __restrict__ bm, float* __restrict__ out)
{
    extern __shared__ float sm[];
    float* AsA = sm;
    float* BsA = sm + 2 * AS_SZ;
    float* AsB = sm + 2 * AS_SZ + 2 * BS_SZ;
    float* BsB = AsB + 2 * AS_SZ;

    const int tid = threadIdx.x;
    const int bid = blockIdx.x;

    // ---- startup (full block): reset counters, zero g_c, out[0]=bm ----
    if (bid == 0 && tid == 0) {
#pragma unroll
        for (int i = 0; i < 8; i++) { cnt_c[i] = 0; cnt_out[i] = 0; cnt_init[i] = 0; }
    }
    {
        int ft = bid * NTF + tid;          // [0, 65536)
        g_c[ft] = 0.0f;
        int col = (ft * 2) & (MDIM - 1);
        *(float2*)(out + (size_t)ft * 2) = *(const float2*)(bm + col);
    }
    grid_barrier();

    if (tid < 256) {
        // ============ HALF A: phase1 + bm-init + copies + phase3 overflow ============
        const int l = tid;
        const bool lead = (l == 0);
        const int ty = l >> 5, tx = l & 31;
        const int arow = l >> 2, akl = (l & 3) << 2;
        int eo[8], eI[8];
#pragma unroll
        for (int j = 0; j < 8; j++) { eo[j] = 0; eI[j] = 0; }

        for (int t = 0; t < T_STEPS; t++) {
            const float* mP  = t ? (out + (size_t)(t - 1) * BM) : m_prev;
            const float* mPP = (t >= 2) ? (out + (size_t)(t - 2) * BM) : m_prev;
            const int kcur  = kval_d(t);
            const int kprev = (t <= 1) ? 8 : kval_d(t - 1);
            const int sp3   = sp3_of(kcur);
            const int units = 2 * kcur * sp3;

            // ---- phase1: red(dm @ Wmh.T) into g_c ----
            {
                const int ct4 = bid >> 4, s = bid & 15;
                const int kb0 = s * (kprev << 4);
                const int colBase = ct4 * 128;
                float4 aR = make_float4(0.f,0.f,0.f,0.f);
                float4 bR0, bR1;
                // prefetch weights chunk 0 before the waits
                bR0 = *(const float4*)(Wmh + (size_t)(colBase + arow) * MDIM + kb0 + akl);
                bR1 = *(const float4*)(Wmh + (size_t)(colBase + 64 + arow) * MDIM + kb0 + akl);
                if (t && lead) {
                    for (int j = 0; j < kprev; j++)
                        while (ldacq(&cnt_out[j]) < (unsigned)eo[j]) { }
                }
                halfbar(1);
                unsigned long long acc[8][2];
#pragma unroll
                for (int r = 0; r < 8; r++) { acc[r][0] = 0ULL; acc[r][1] = 0ULL; }

#define P1_LOADA(CH) do { int kb = kb0 + ((CH) << 4);                                      \
    if (t) {                                                                               \
        float4 p = __ldcg((const float4*)(mP  + (size_t)arow * MDIM + kb + akl));          \
        float4 q = __ldcg((const float4*)(mPP + (size_t)arow * MDIM + kb + akl));          \
        aR = make_float4(p.x - q.x, p.y - q.y, p.z - q.z, p.w - q.w);                      \
    } else {                                                                               \
        aR = *(const float4*)(m_prev + (size_t)arow * MDIM + kb + akl);                    \
    }                                                                                      \
} while (0)
#define P1_LOADB(CH) do { int kb = kb0 + ((CH) << 4);                                      \
    bR0 = *(const float4*)(Wmh + (size_t)(colBase + arow) * MDIM + kb + akl);              \
    bR1 = *(const float4*)(Wmh + (size_t)(colBase + 64 + arow) * MDIM + kb + akl);         \
} while (0)

                P1_LOADA(0); PX_STORE(AsA, BsA, 0); halfbar(1);
                for (int ch = 0; ch < kprev; ch++) {
                    if (ch + 1 < kprev) { P1_LOADB(ch + 1); P1_LOADA(ch + 1); }
                    tile82(AsA + (ch & 1) * AS_SZ, BsA + (ch & 1) * BS_SZ, ty, tx, acc);
                    if (ch + 1 < kprev) { PX_STORE(AsA, BsA, (ch + 1) & 1); halfbar(1); }
                }
#pragma unroll
                for (int r = 0; r < 8; r++) {
                    float2 a0 = *(float2*)&acc[r][0], a1 = *(float2*)&acc[r][1];
                    red_add_v4(g_c + (size_t)(ty * 8 + r) * HID + colBase + tx * 4,
                               make_float4(a0.x, a0.y, a1.x, a1.y));
                }
                __threadfence();
                halfbar(1);
                if (lead) atomicAdd(&cnt_c[ct4], 1u);
            }

            // ---- bm-init out[t+1] active tiles ----
            if (t + 1 < T_STEPS) {
                int kn = kval_d(t + 1);
                int j = bid - 120;
                if (j >= 0 && j < kn) {
                    float* dst = out + (size_t)(t + 1) * BM;
                    for (int idx = l; idx < 4096; idx += 256) {
                        int row = idx >> 6, c4 = (idx & 63) << 2;
                        *(float4*)(dst + (size_t)row * MDIM + j * 256 + c4) =
                            *(const float4*)(bm + j * 256 + c4);
                    }
                    __threadfence();
                    halfbar(1);
                    if (lead) atomicAdd(&cnt_init[j], 1u);
                }
            }

            // ---- copies: inactive tiles (wait = RAW + signal ordering) ----
            {
                const int ct8 = bid >> 4, part = bid & 15;
                if (ct8 >= kcur) {
                    if (lead) { while (ldacq(&cnt_out[ct8]) < (unsigned)eo[ct8]) { } }
                    halfbar(1);
                    int row = l >> 2;
                    int col = ct8 * 256 + part * 16 + (l & 3) * 4;
                    size_t moff = (size_t)row * MDIM + col;
                    float4 v = __ldcg((const float4*)(mP + moff));
                    *(float4*)(out + (size_t)t * BM + moff) = v;
                    __threadfence();
                    halfbar(1);
                    if (lead) atomicAdd(&cnt_out[ct8], 1u);
                }
            }

            // ---- phase3 overflow units ----
            if (128 + bid < units) {
                const int unit = 128 + bid;
                PHASE3_BODY(AsA, BsA, 1);
            }

            // ---- bookkeeping ----
            {
                const int as = 2 * sp3;
#pragma unroll
                for (int j = 0; j < 8; j++) eo[j] += (j < kcur) ? as : 16;
                if (t + 1 < T_STEPS) {
                    int kn = kval_d(t + 1);
#pragma unroll
                    for (int j = 0; j < 8; j++) if (j < kn) eI[j]++;
                }
            }
        }

        // ---- final: m_T = out[255] ----
        if (lead) {
#pragma unroll
            for (int j = 0; j < 8; j++)
                while (ldacq(&cnt_out[j]) < (unsigned)eo[j]) { }
        }
        halfbar(1);
        {
            int ft2 = bid * 256 + l;      // [0, 32768)
            float4 v = __ldcg((const float4*)(out + (size_t)(T_STEPS - 1) * BM + (size_t)ft2 * 4));
            *(float4*)(out + (size_t)T_STEPS * BM + (size_t)ft2 * 4) = v;
        }
    } else {
        // ============ HALF B: phase3 main units ============
        const int l = tid - 256;
        const bool lead = (l == 0);
        const int ty = l >> 5, tx = l & 31;
        const int arow = l >> 2, akl = (l & 3) << 2;
        int eo[8], eI[8];
#pragma unroll
        for (int j = 0; j < 8; j++) { eo[j] = 0; eI[j] = 0; }

        for (int t = 0; t < T_STEPS; t++) {
            const float* mP = t ? (out + (size_t)(t - 1) * BM) : m_prev;
            const int kcur = kval_d(t);
            const int sp3 = sp3_of(kcur);
            const int units = 2 * kcur * sp3;
            if (bid < units) {      // always true (units >= 128), kept for safety
                const int unit = bid;
                PHASE3_BODY(AsB, BsB, 2);
            }
            // ---- bookkeeping ----
            {
                const int as = 2 * sp3;
#pragma unroll
                for (int j = 0; j < 8; j++) eo[j] += (j < kcur) ? as : 16;
                if (t + 1 < T_STEPS) {
                    int kn = kval_d(t + 1);
#pragma unroll
                    for (int j = 0; j < 8; j++) if (j < kn) eI[j]++;
                }
            }
        }
    }
}

// ---------------- host ----------------
extern "C" void kernel_launch(void* const* d_in, const int* in_sizes, int n_in,
                              void* d_out, int out_size)
{
    const float* x      = (const float*)d_in[0];
    const float* m_prev = (const float*)d_in[1];
    const float* Wxh    = (const float*)d_in[2];
    const float* Whm    = (const float*)d_in[3];
    const float* Wmm    = (const float*)d_in[4];
    const float* Wmh    = (const float*)d_in[5];
    const float* bm     = (const float*)d_in[6];
    const float* bh     = (const float*)d_in[7];
    float* out = (float*)d_out;
    (void)in_sizes; (void)n_in; (void)out_size;

    cudaFuncSetAttribute(rnn_persistent,
                         cudaFuncAttributeMaxDynamicSharedMemorySize,
                         SMEM_FLOATS * sizeof(float));

    xh_kernel<<<dim3(4, 256), 256>>>(x, Wxh, bh);
    rnn_persistent<<<NB, NTF, SMEM_FLOATS * sizeof(float)>>>(m_prev, Wmh, Wmm, Whm, bm, out);
}

// round 17
// speedup vs baseline: 1.1617x; 1.0455x over previous
#include <cuda_runtime.h>

#define T_STEPS 256
#define BATCH   64
#define IN_DIM  512
#define HID     1024
#define MDIM    2048
#define NB      128
#define NTF     512
#define BM      (BATCH*MDIM)   // 131072
#define BH      (BATCH*HID)    // 65536
#define AS_STR  68
#define BS_STR  132
#define AS_SZ   (16*AS_STR)    // 1088 floats
#define BS_SZ   (16*BS_STR)    // 2112 floats
#define SMEM_FLOATS (4*AS_SZ + 4*BS_SZ)   // 12800 floats = 51200 B

// ---------------- static device scratch ----------------
__device__ float g_xh[(size_t)T_STEPS * BH];  // x@Wxh + bh (64 MB)
__device__ float g_c[BH];                     // running c = m @ Wmh.T (red-accumulated)
__device__ unsigned g_cnt, g_gen;
__device__ unsigned cnt_c[8];     // per 128-col c tile: phase1 units done (16/step)
__device__ unsigned cnt_out[8];   // per 256-col out tile completion (step-ordered)
__device__ unsigned cnt_init[8];  // per 256-col out tile bm-init events

// ---------------- packed fp32x2 ----------------
__device__ __forceinline__ unsigned long long pack2(float a) {
    unsigned long long r;
    asm("mov.b64 %0, {%1, %1};" : "=l"(r) : "f"(a));
    return r;
}
__device__ __forceinline__ void ffma2(unsigned long long& c, unsigned long long a, unsigned long long b) {
    asm("fma.rn.f32x2 %0, %1, %2, %0;" : "+l"(c) : "l"(a), "l"(b));
}

// ---------------- L2-side vector reduction ----------------
__device__ __forceinline__ void red_add_v4(float* p, float4 v) {
    asm volatile("red.global.add.v4.f32 [%0], {%1,%2,%3,%4};"
                 :: "l"(p), "f"(v.x), "f"(v.y), "f"(v.z), "f"(v.w) : "memory");
}

// ---------------- sync primitives ----------------
__device__ __forceinline__ unsigned ldacq(const unsigned* p) {
    unsigned v;
    asm volatile("ld.acquire.gpu.global.u32 %0, [%1];" : "=r"(v) : "l"(p) : "memory");
    return v;
}
__device__ __forceinline__ void halfbar(int id) {
    asm volatile("bar.sync %0, %1;" :: "r"(id), "r"(256) : "memory");
}
__device__ __forceinline__ void grid_barrier() {
    __threadfence();
    __syncthreads();
    if (threadIdx.x == 0) {
        volatile unsigned* vg = &g_gen;
        unsigned old = *vg;
        unsigned prev = atomicAdd(&g_cnt, 1u);
        if (prev == NB - 1) {
            atomicExch(&g_cnt, 0u);
            __threadfence();
            atomicAdd(&g_gen, 1u);
        } else {
            while (*vg == old) { __nanosleep(64); }
        }
    }
    __syncthreads();
}

__device__ __forceinline__ int kval_d(int t) { return t ? min(__ffs(t), 8) : 8; }
// units = 2*k*sp3; Kc = 3072/sp3 is a multiple of 16
__device__ __forceinline__ int sp3_of(int k) {
    return (k == 1) ? 96 : (k == 2) ? 64 : (k <= 4) ? 32 : (k == 5) ? 24 : 16;
}

// ---------------- tile compute: 64 rows x 128 cols, 256 thr, 8x4 ----------
__device__ __forceinline__ void tile82(const float* As, const float* Bs,
                                       int ty, int tx, unsigned long long acc[8][2]) {
#pragma unroll
    for (int kk = 0; kk < 16; kk++) {
        float4 a0 = *(const float4*)(As + kk * AS_STR + ty * 8);
        float4 a1 = *(const float4*)(As + kk * AS_STR + ty * 8 + 4);
        const unsigned long long* bp = (const unsigned long long*)(Bs + kk * BS_STR + tx * 4);
        unsigned long long b0 = bp[0], b1 = bp[1];
        float as[8] = {a0.x, a0.y, a0.z, a0.w, a1.x, a1.y, a1.z, a1.w};
#pragma unroll
        for (int r = 0; r < 8; r++) {
            unsigned long long av = pack2(as[r]);
            ffma2(acc[r][0], av, b0);
            ffma2(acc[r][1], av, b1);
        }
    }
}
// ---------------- 64x256, 256 thr, 8x8 (prologue only) ----------
__device__ __forceinline__ void tile_compute8(const float* As, const float* Bs,
                                              int ty, int tx, unsigned long long acc[8][4]) {
#pragma unroll
    for (int kk = 0; kk < 16; kk++) {
        float4 a0 = *(const float4*)(As + kk * 68 + ty * 8);
        float4 a1 = *(const float4*)(As + kk * 68 + ty * 8 + 4);
        const unsigned long long* bp = (const unsigned long long*)(Bs + kk * 260 + tx * 8);
        unsigned long long b0 = bp[0], b1 = bp[1], b2 = bp[2], b3 = bp[3];
        float as[8] = {a0.x, a0.y, a0.z, a0.w, a1.x, a1.y, a1.z, a1.w};
#pragma unroll
        for (int r = 0; r < 8; r++) {
            unsigned long long av = pack2(as[r]);
            ffma2(acc[r][0], av, b0);
            ffma2(acc[r][1], av, b1);
            ffma2(acc[r][2], av, b2);
            ffma2(acc[r][3], av, b3);
        }
    }
}

// ---------------- prologue: g_xh = x @ Wxh + bh ----------------
__global__ __launch_bounds__(256) void xh_kernel(
    const float* __restrict__ X, const float* __restrict__ Wxh, const float* __restrict__ bh)
{
    __shared__ float As[16 * 68];
    __shared__ float Bs[16 * 260];
    const int tid = threadIdx.x;
    const int ty = tid >> 5, tx = tid & 31;
    const int colBase = blockIdx.x * 256;
    const int rowBase = blockIdx.y * 64;

    unsigned long long acc[8][4];
#pragma unroll
    for (int r = 0; r < 8; r++)
#pragma unroll
        for (int c = 0; c < 4; c++) acc[r][c] = 0ULL;

    for (int ch = 0; ch < 32; ch++) {
        int kb = ch << 4;
        {
            int row = tid >> 2, kl = (tid & 3) << 2;
            float4 v = *(const float4*)(X + (size_t)(rowBase + row) * IN_DIM + kb + kl);
            As[(kl + 0) * 68 + row] = v.x; As[(kl + 1) * 68 + row] = v.y;
            As[(kl + 2) * 68 + row] = v.z; As[(kl + 3) * 68 + row] = v.w;
        }
#pragma unroll
        for (int i = 0; i < 4; i++) {
            int g = tid + i * 256;
            int kl = g >> 6, col4 = (g & 63) << 2;
            float4 v = *(const float4*)(Wxh + (size_t)(kb + kl) * HID + colBase + col4);
            *(float4*)(Bs + kl * 260 + col4) = v;
        }
        __syncthreads();
        tile_compute8(As, Bs, ty, tx, acc);
        __syncthreads();
    }
#pragma unroll
    for (int r = 0; r < 8; r++) {
        int row = rowBase + ty * 8 + r;
        int jg = colBase + tx * 8;
#pragma unroll
        for (int c = 0; c < 4; c++) {
            float2 v = *(float2*)&acc[r][c];
            float2 bb = *(const float2*)(bh + jg + c * 2);
            v.x += bb.x; v.y += bb.y;
            *(float2*)(g_xh + (size_t)row * HID + jg + c * 2) = v;
        }
    }
}

// ======== phase-3 unit body (shared by both halves via macro) ========
// uses from scope: unit, t, kcur, sp3, mP, Wmm, Whm, out, eo, eI, lead,
// ty, tx, arow, akl
#define P3_LOADB(CH) do { int kb = kb0 + ((CH) << 4);                                      \
    { int jg = colBase + arow;                                                             \
      bR0 = (kb < MDIM) ? *(const float4*)(Wmm + (size_t)jg * MDIM + kb + akl)             \
                        : *(const float4*)(Whm + (size_t)jg * HID + (kb - MDIM) + akl); }  \
    { int jg = colBase + 64 + arow;                                                        \
      bR1 = (kb < MDIM) ? *(const float4*)(Wmm + (size_t)jg * MDIM + kb + akl)             \
                        : *(const float4*)(Whm + (size_t)jg * HID + (kb - MDIM) + akl); }  \
} while (0)

#define P3_LOADA(CH) do { int kb = kb0 + ((CH) << 4);                                      \
    if (kb < MDIM) {                                                                       \
        aR = __ldcg((const float4*)(mP + (size_t)arow * MDIM + kb + akl));                 \
    } else {                                                                               \
        size_t hoff = (size_t)arow * HID + (kb - MDIM) + akl;                              \
        float4 cc = __ldcg((const float4*)(g_c + hoff));                                   \
        float4 xx = *(const float4*)(g_xh + (size_t)t * BH + hoff);                        \
        aR = make_float4(tanhf(xx.x + cc.x), tanhf(xx.y + cc.y),                           \
                         tanhf(xx.z + cc.z), tanhf(xx.w + cc.w));                          \
    }                                                                                      \
} while (0)

#define PX_STORE(AP, BP, BF) do { float* A_ = (AP) + (BF) * AS_SZ; float* B_ = (BP) + (BF) * BS_SZ; \
    A_[(akl + 0) * AS_STR + arow] = aR.x; A_[(akl + 1) * AS_STR + arow] = aR.y;            \
    A_[(akl + 2) * AS_STR + arow] = aR.z; A_[(akl + 3) * AS_STR + arow] = aR.w;            \
    B_[(akl + 0) * BS_STR + arow] = bR0.x; B_[(akl + 1) * BS_STR + arow] = bR0.y;          \
    B_[(akl + 2) * BS_STR + arow] = bR0.z; B_[(akl + 3) * BS_STR + arow] = bR0.w;          \
    B_[(akl + 0) * BS_STR + 64 + arow] = bR1.x; B_[(akl + 1) * BS_STR + 64 + arow] = bR1.y;\
    B_[(akl + 2) * BS_STR + 64 + arow] = bR1.z; B_[(akl + 3) * BS_STR + 64 + arow] = bR1.w;\
} while (0)

#define PHASE3_BODY(AP, BP, BARID)                                                         \
{                                                                                          \
    const int Kc3 = 3072 / sp3;                                                            \
    const int chunks = Kc3 >> 4;                                                           \
    const int t128 = unit / sp3;                                                           \
    const int s = unit - t128 * sp3;                                                       \
    const int colBase = t128 * 128;                                                        \
    const int ct256 = t128 >> 1;                                                           \
    const int kb0 = s * Kc3;                                                               \
    const int kend = kb0 + Kc3;                                                            \
    const int hstart = (kb0 >= MDIM) ? 0 : ((kend <= MDIM) ? chunks : ((MDIM - kb0) >> 4));\
    float4 aR = make_float4(0.f,0.f,0.f,0.f);                                              \
    float4 bR0, bR1;                                                                       \
    P3_LOADB(0);   /* weight prefetch overlaps the waits */                                \
    if (lead) {                                                                            \
        while (ldacq(&cnt_init[ct256]) < (unsigned)eI[ct256]) { }                          \
        const int mk1 = min(kend, MDIM);                                                   \
        if (t && mk1 > kb0) {                                                              \
            const int jlo = kb0 >> 8, jhi = (mk1 - 1) >> 8;                                \
            for (int j = jlo; j <= jhi; j++)                                               \
                while (ldacq(&cnt_out[j]) < (unsigned)eo[j]) { }                           \
        }                                                                                  \
        if (hstart == 0) {                                                                 \
            const int jlo = (kb0 - MDIM) >> 7, jhi = (kend - 1 - MDIM) >> 7;               \
            for (int j = jlo; j <= jhi; j++)                                               \
                while (ldacq(&cnt_c[j]) < 16u * (unsigned)(t + 1)) { }                     \
        }                                                                                  \
    }                                                                                      \
    halfbar(BARID);                                                                        \
    unsigned long long acc[8][2];                                                          \
    _Pragma("unroll")                                                                      \
    for (int r = 0; r < 8; r++) { acc[r][0] = 0ULL; acc[r][1] = 0ULL; }                    \
    P3_LOADA(0); PX_STORE(AP, BP, 0); halfbar(BARID);                                      \
    for (int ch = 0; ch < chunks; ch++) {                                                  \
        if (ch + 1 < chunks) {                                                             \
            if (ch + 1 == hstart) {                                                        \
                if (lead) {                                                                \
                    const int jhi2 = (kend - 1 - MDIM) >> 7;                               \
                    for (int j = 0; j <= jhi2; j++)                                        \
                        while (ldacq(&cnt_c[j]) < 16u * (unsigned)(t + 1)) { }             \
                }                                                                          \
                halfbar(BARID);                                                            \
            }                                                                              \
            P3_LOADB(ch + 1); P3_LOADA(ch + 1);                                            \
        }                                                                                  \
        tile82((AP) + (ch & 1) * AS_SZ, (BP) + (ch & 1) * BS_SZ, ty, tx, acc);             \
        if (ch + 1 < chunks) { PX_STORE(AP, BP, (ch + 1) & 1); halfbar(BARID); }           \
    }                                                                                      \
    {                                                                                      \
        float* obase = out + (size_t)t * BM;                                               \
        _Pragma("unroll")                                                                  \
        for (int r = 0; r < 8; r++) {                                                      \
            float2 a0 = *(float2*)&acc[r][0], a1 = *(float2*)&acc[r][1];                   \
            red_add_v4(obase + (size_t)(ty * 8 + r) * MDIM + colBase + tx * 4,             \
                       make_float4(a0.x, a0.y, a1.x, a1.y));                               \
        }                                                                                  \
    }                                                                                      \
    /* step-ordering poll + fence + single bar + signal */                                 \
    if (lead) { while (ldacq(&cnt_out[ct256]) < (unsigned)eo[ct256]) { } }                 \
    __threadfence();                                                                       \
    halfbar(BARID);                                                                        \
    if (lead) atomicAdd(&cnt_out[ct256], 1u);                                              \
}

// ---------------- persistent dataflow recurrence (warp-specialized halves) ----
__global__ __launch_bounds__(NTF, 1) void rnn_persistent(
    const float* __restrict__ m_prev, const float* __restrict__ Wmh,
    const float* __restrict__ Wmm, const float* __restrict__ Whm,
    const float* __restrict__ bm, float* __restrict__ out)
{
    extern __shared__ float sm[];
    float* AsA = sm;
    float* BsA = sm + 2 * AS_SZ;
    float* AsB = sm + 2 * AS_SZ + 2 * BS_SZ;
    float* BsB = AsB + 2 * AS_SZ;

    const int tid = threadIdx.x;
    const int bid = blockIdx.x;

    // ---- startup (full block): reset counters, zero g_c, out[0]=bm ----
    if (bid == 0 && tid == 0) {
#pragma unroll
        for (int i = 0; i < 8; i++) { cnt_c[i] = 0; cnt_out[i] = 0; cnt_init[i] = 0; }
    }
    {
        int ft = bid * NTF + tid;          // [0, 65536)
        g_c[ft] = 0.0f;
        int col = (ft * 2) & (MDIM - 1);
        *(float2*)(out + (size_t)ft * 2) = *(const float2*)(bm + col);
    }
    grid_barrier();

    if (tid < 256) {
        // ============ HALF A: phase1 + bm-init + copies + phase3 overflow ============
        const int l = tid;
        const bool lead = (l == 0);
        const int ty = l >> 5, tx = l & 31;
        const int arow = l >> 2, akl = (l & 3) << 2;
        int eo[8], eI[8];
#pragma unroll
        for (int j = 0; j < 8; j++) { eo[j] = 0; eI[j] = 0; }

        for (int t = 0; t < T_STEPS; t++) {
            const float* mP  = t ? (out + (size_t)(t - 1) * BM) : m_prev;
            const float* mPP = (t >= 2) ? (out + (size_t)(t - 2) * BM) : m_prev;
            const int kcur  = kval_d(t);
            const int kprev = (t <= 1) ? 8 : kval_d(t - 1);
            const int sp3   = sp3_of(kcur);
            const int units = 2 * kcur * sp3;

            // ---- phase1: red(dm @ Wmh.T) into g_c ----
            {
                const int ct4 = bid >> 4, s = bid & 15;
                const int kb0 = s * (kprev << 4);
                const int colBase = ct4 * 128;
                float4 aR = make_float4(0.f,0.f,0.f,0.f);
                float4 bR0, bR1;
                // prefetch weights chunk 0 before the waits
                bR0 = *(const float4*)(Wmh + (size_t)(colBase + arow) * MDIM + kb0 + akl);
                bR1 = *(const float4*)(Wmh + (size_t)(colBase + 64 + arow) * MDIM + kb0 + akl);
                if (t && lead) {
                    for (int j = 0; j < kprev; j++)
                        while (ldacq(&cnt_out[j]) < (unsigned)eo[j]) { }
                }
                halfbar(1);
                unsigned long long acc[8][2];
#pragma unroll
                for (int r = 0; r < 8; r++) { acc[r][0] = 0ULL; acc[r][1] = 0ULL; }

#define P1_LOADA(CH) do { int kb = kb0 + ((CH) << 4);                                      \
    if (t) {                                                                               \
        float4 p = __ldcg((const float4*)(mP  + (size_t)arow * MDIM + kb + akl));          \
        float4 q = __ldcg((const float4*)(mPP + (size_t)arow * MDIM + kb + akl));          \
        aR = make_float4(p.x - q.x, p.y - q.y, p.z - q.z, p.w - q.w);                      \
    } else {                                                                               \
        aR = *(const float4*)(m_prev + (size_t)arow * MDIM + kb + akl);                    \
    }                                                                                      \
} while (0)
#define P1_LOADB(CH) do { int kb = kb0 + ((CH) << 4);                                      \
    bR0 = *(const float4*)(Wmh + (size_t)(colBase + arow) * MDIM + kb + akl);              \
    bR1 = *(const float4*)(Wmh + (size_t)(colBase + 64 + arow) * MDIM + kb + akl);         \
} while (0)

                P1_LOADA(0); PX_STORE(AsA, BsA, 0); halfbar(1);
                for (int ch = 0; ch < kprev; ch++) {
                    if (ch + 1 < kprev) { P1_LOADB(ch + 1); P1_LOADA(ch + 1); }
                    tile82(AsA + (ch & 1) * AS_SZ, BsA + (ch & 1) * BS_SZ, ty, tx, acc);
                    if (ch + 1 < kprev) { PX_STORE(AsA, BsA, (ch + 1) & 1); halfbar(1); }
                }
#pragma unroll
                for (int r = 0; r < 8; r++) {
                    float2 a0 = *(float2*)&acc[r][0], a1 = *(float2*)&acc[r][1];
                    red_add_v4(g_c + (size_t)(ty * 8 + r) * HID + colBase + tx * 4,
                               make_float4(a0.x, a0.y, a1.x, a1.y));
                }
                __threadfence();
                halfbar(1);
                if (lead) atomicAdd(&cnt_c[ct4], 1u);
            }

            // ---- bm-init out[t+1] active tiles ----
            if (t + 1 < T_STEPS) {
                int kn = kval_d(t + 1);
                int j = bid - 120;
                if (j >= 0 && j < kn) {
                    float* dst = out + (size_t)(t + 1) * BM;
                    for (int idx = l; idx < 4096; idx += 256) {
                        int row = idx >> 6, c4 = (idx & 63) << 2;
                        *(float4*)(dst + (size_t)row * MDIM + j * 256 + c4) =
                            *(const float4*)(bm + j * 256 + c4);
                    }
                    __threadfence();
                    halfbar(1);
                    if (lead) atomicAdd(&cnt_init[j], 1u);
                }
            }

            // ---- copies: inactive tiles (wait = RAW + signal ordering) ----
            {
                const int ct8 = bid >> 4, part = bid & 15;
                if (ct8 >= kcur) {
                    if (lead) { while (ldacq(&cnt_out[ct8]) < (unsigned)eo[ct8]) { } }
                    halfbar(1);
                    int row = l >> 2;
                    int col = ct8 * 256 + part * 16 + (l & 3) * 4;
                    size_t moff = (size_t)row * MDIM + col;
                    float4 v = __ldcg((const float4*)(mP + moff));
                    *(float4*)(out + (size_t)t * BM + moff) = v;
                    __threadfence();
                    halfbar(1);
                    if (lead) atomicAdd(&cnt_out[ct8], 1u);
                }
            }

            // ---- phase3 overflow units ----
            if (kcur == 1) {
                // remapped: half A gets only pure-m units s=32..63 of each 128-half
                if (bid < 64) {
                    const int unit = (bid >> 5) * 96 + 32 + (bid & 31);
                    PHASE3_BODY(AsA, BsA, 1);
                }
            } else if (128 + bid < units) {
                const int unit = 128 + bid;
                PHASE3_BODY(AsA, BsA, 1);
            }

            // ---- bookkeeping ----
            {
                const int as = 2 * sp3;
#pragma unroll
                for (int j = 0; j < 8; j++) eo[j] += (j < kcur) ? as : 16;
                if (t + 1 < T_STEPS) {
                    int kn = kval_d(t + 1);
#pragma unroll
                    for (int j = 0; j < 8; j++) if (j < kn) eI[j]++;
                }
            }
        }

        // ---- final: m_T = out[255] ----
        if (lead) {
#pragma unroll
            for (int j = 0; j < 8; j++)
                while (ldacq(&cnt_out[j]) < (unsigned)eo[j]) { }
        }
        halfbar(1);
        {
            int ft2 = bid * 256 + l;      // [0, 32768)
            float4 v = __ldcg((const float4*)(out + (size_t)(T_STEPS - 1) * BM + (size_t)ft2 * 4));
            *(float4*)(out + (size_t)T_STEPS * BM + (size_t)ft2 * 4) = v;
        }
    } else {
        // ============ HALF B: phase3 main units ============
        const int l = tid - 256;
        const bool lead = (l == 0);
        const int ty = l >> 5, tx = l & 31;
        const int arow = l >> 2, akl = (l & 3) << 2;
        int eo[8], eI[8];
#pragma unroll
        for (int j = 0; j < 8; j++) { eo[j] = 0; eI[j] = 0; }

        for (int t = 0; t < T_STEPS; t++) {
            const float* mP = t ? (out + (size_t)(t - 1) * BM) : m_prev;
            const int kcur = kval_d(t);
            const int sp3 = sp3_of(kcur);
            const int units = 2 * kcur * sp3;
            if (kcur == 1) {
                // remapped: half B gets all h-units (s=64..95) + m-units s=0..31
                int unit;
                if (bid < 32)       unit = 64 + bid;            // t128=0, s=64..95 (h)
                else if (bid < 64)  unit = 128 + bid;           // t128=1, s=64..95 (h)
                else if (bid < 96)  unit = bid - 64;            // t128=0, s=0..31  (m)
                else                unit = bid;                 // t128=1, s=0..31  (m)
                PHASE3_BODY(AsB, BsB, 2);
            } else if (bid < units) {
                const int unit = bid;
                PHASE3_BODY(AsB, BsB, 2);
            }
            // ---- bookkeeping ----
            {
                const int as = 2 * sp3;
#pragma unroll
                for (int j = 0; j < 8; j++) eo[j] += (j < kcur) ? as : 16;
                if (t + 1 < T_STEPS) {
                    int kn = kval_d(t + 1);
#pragma unroll
                    for (int j = 0; j < 8; j++) if (j < kn) eI[j]++;
                }
            }
        }
    }
}

// ---------------- host ----------------
extern "C" void kernel_launch(void* const* d_in, const int* in_sizes, int n_in,
                              void* d_out, int out_size)
{
    const float* x      = (const float*)d_in[0];
    const float* m_prev = (const float*)d_in[1];
    const float* Wxh    = (const float*)d_in[2];
    const float* Whm    = (const float*)d_in[3];
    const float* Wmm    = (const float*)d_in[4];
    const float* Wmh    = (const float*)d_in[5];
    const float* bm     = (const float*)d_in[6];
    const float* bh     = (const float*)d_in[7];
    float* out = (float*)d_out;
    (void)in_sizes; (void)n_in; (void)out_size;

    cudaFuncSetAttribute(rnn_persistent,
                         cudaFuncAttributeMaxDynamicSharedMemorySize,
                         SMEM_FLOATS * sizeof(float));

    xh_kernel<<<dim3(4, 256), 256>>>(x, Wxh, bh);
    rnn_persistent<<<NB, NTF, SMEM_FLOATS * sizeof(float)>>>(m_prev, Wmh, Wmm, Whm, bm, out);
}